// round 1
// baseline (speedup 1.0000x reference)
#include <cuda_runtime.h>
#include <cuda_bf16.h>

// Problem constants (fixed by the reference: N=4096, A=256, D_IN=39, H=50, S=8)
#define NROWS  4096
#define NATOM  256
#define DIN    39
#define HDIM   50

#define TILE_N 128           // rows per block
#define XP     41            // desc tile row pitch (41 % 32 = 9, coprime -> conflict-free)
#define HP     51            // hidden tile row pitch (51 % 32 = 19, coprime)
#define WP     56            // weight row pitch (cols padded 50 -> 56)
#define RPT    4             // rows per thread
#define CPT    7             // cols per thread (8 thread-cols * 7 = 56)
#define NTHREADS 256         // 32 thread-rows (ty) x 8 thread-cols (tx)

// Shared memory layout (floats):
//   W1s[DIN*WP]  W2s[HDIM*WP]  b1s[WP]  b2s[WP]  W3s[WP]  b3s[8]
//   Xs[TILE_N*XP]  H1s[TILE_N*HP]
#define OFF_W1  0
#define OFF_W2  (OFF_W1 + DIN*WP)          // 2184
#define OFF_B1  (OFF_W2 + HDIM*WP)         // 2184+2800 = 4984
#define OFF_B2  (OFF_B1 + WP)
#define OFF_W3  (OFF_B2 + WP)
#define OFF_B3  (OFF_W3 + WP)
#define OFF_X   (OFF_B3 + 8)
#define OFF_H1  (OFF_X + TILE_N*XP)
#define SMEM_FLOATS (OFF_H1 + TILE_N*HP)
#define SMEM_BYTES  (SMEM_FLOATS * 4)

__device__ __forceinline__ float silu_f(float x) {
    // x * sigmoid(x) = x / (1 + e^-x). __expf: ~2 ulp, well within 1e-3 budget.
    return x / (1.0f + __expf(-x));
}

__global__ __launch_bounds__(NTHREADS)
void atomic_mlp_kernel(const float* __restrict__ desc,
                       const int*   __restrict__ numbers,
                       const float* __restrict__ W1,
                       const float* __restrict__ b1,
                       const float* __restrict__ W2,
                       const float* __restrict__ b2,
                       const float* __restrict__ W3,
                       const float* __restrict__ b3,
                       float* __restrict__ out)
{
    extern __shared__ float sm[];
    float* W1s = sm + OFF_W1;
    float* W2s = sm + OFF_W2;
    float* b1s = sm + OFF_B1;
    float* b2s = sm + OFF_B2;
    float* W3s = sm + OFF_W3;
    float* b3s = sm + OFF_B3;
    float* Xs  = sm + OFF_X;
    float* H1s = sm + OFF_H1;

    const int a   = blockIdx.y;
    const int n0  = blockIdx.x * TILE_N;
    const int tid = threadIdx.x;
    const int s   = numbers[a];

    // ---- Stage weights for this species into smem (padded pitch WP) ----
    {
        const float* W1g = W1 + s * (DIN * HDIM);
        #pragma unroll 4
        for (int i = tid; i < DIN * HDIM; i += NTHREADS) {
            int k = i / HDIM, j = i - k * HDIM;
            W1s[k * WP + j] = W1g[i];
        }
        const float* W2g = W2 + s * (HDIM * HDIM);
        #pragma unroll 4
        for (int i = tid; i < HDIM * HDIM; i += NTHREADS) {
            int k = i / HDIM, j = i - k * HDIM;
            W2s[k * WP + j] = W2g[i];
        }
        if (tid < WP) {
            float v1 = 0.f, v2 = 0.f, v3 = 0.f;
            if (tid < HDIM) {
                v1 = b1[s * HDIM + tid];
                v2 = b2[s * HDIM + tid];
                v3 = W3[s * HDIM + tid];
            }
            b1s[tid] = v1; b2s[tid] = v2; W3s[tid] = v3;
        }
        if (tid == 0) b3s[0] = b3[s];
    }

    // ---- Stage desc tile: rows n0..n0+127 of atom a ----
    {
        const float* Xg = desc + ((size_t)n0 * NATOM + a) * DIN;
        #pragma unroll 4
        for (int i = tid; i < TILE_N * DIN; i += NTHREADS) {
            int r = i / DIN, k = i - r * DIN;
            Xs[r * XP + k] = Xg[(size_t)r * (NATOM * DIN) + k];
        }
    }
    __syncthreads();

    const int ty = tid >> 3;          // 0..31
    const int tx = tid & 7;           // 0..7
    const int row0 = ty * RPT;        // 0..124
    const int col0 = tx * CPT;        // 0..49

    // ================= Layer 1: H1 = silu(X @ W1 + b1) =================
    {
        float acc[RPT][CPT];
        #pragma unroll
        for (int i = 0; i < RPT; ++i)
            #pragma unroll
            for (int j = 0; j < CPT; ++j) acc[i][j] = 0.f;

        #pragma unroll 3
        for (int k = 0; k < DIN; ++k) {
            float av[RPT], bv[CPT];
            #pragma unroll
            for (int i = 0; i < RPT; ++i) av[i] = Xs[(row0 + i) * XP + k];
            #pragma unroll
            for (int j = 0; j < CPT; ++j) bv[j] = W1s[k * WP + col0 + j];
            #pragma unroll
            for (int i = 0; i < RPT; ++i)
                #pragma unroll
                for (int j = 0; j < CPT; ++j)
                    acc[i][j] = fmaf(av[i], bv[j], acc[i][j]);
        }

        #pragma unroll
        for (int i = 0; i < RPT; ++i) {
            #pragma unroll
            for (int j = 0; j < CPT; ++j) {
                int c = col0 + j;
                if (c < HDIM) {
                    float h = acc[i][j] + b1s[c];
                    H1s[(row0 + i) * HP + c] = silu_f(h);
                }
            }
        }
    }
    __syncthreads();

    // ================= Layer 2: H2 = silu(H1 @ W2 + b2) =================
    {
        float acc[RPT][CPT];
        #pragma unroll
        for (int i = 0; i < RPT; ++i)
            #pragma unroll
            for (int j = 0; j < CPT; ++j) acc[i][j] = 0.f;

        #pragma unroll 2
        for (int k = 0; k < HDIM; ++k) {
            float av[RPT], bv[CPT];
            #pragma unroll
            for (int i = 0; i < RPT; ++i) av[i] = H1s[(row0 + i) * HP + k];
            #pragma unroll
            for (int j = 0; j < CPT; ++j) bv[j] = W2s[k * WP + col0 + j];
            #pragma unroll
            for (int i = 0; i < RPT; ++i)
                #pragma unroll
                for (int j = 0; j < CPT; ++j)
                    acc[i][j] = fmaf(av[i], bv[j], acc[i][j]);
        }

        __syncthreads();   // all reads of H1s done before overwrite

        #pragma unroll
        for (int i = 0; i < RPT; ++i) {
            #pragma unroll
            for (int j = 0; j < CPT; ++j) {
                int c = col0 + j;
                if (c < HDIM) {
                    float h = acc[i][j] + b2s[c];
                    H1s[(row0 + i) * HP + c] = silu_f(h);   // H2 overwrites H1 buffer
                }
            }
        }
    }
    __syncthreads();

    // ================= Layer 3: out = H2 @ w3 + b3 =================
    if (tid < TILE_N) {
        float sum = b3s[0];
        #pragma unroll 5
        for (int k = 0; k < HDIM; ++k)
            sum = fmaf(H1s[tid * HP + k], W3s[k], sum);
        out[(size_t)(n0 + tid) * NATOM + a] = sum;
    }
}

extern "C" void kernel_launch(void* const* d_in, const int* in_sizes, int n_in,
                              void* d_out, int out_size)
{
    const float* desc    = (const float*)d_in[0];
    const int*   numbers = (const int*)  d_in[1];
    const float* W1      = (const float*)d_in[2];
    const float* b1      = (const float*)d_in[3];
    const float* W2      = (const float*)d_in[4];
    const float* b2      = (const float*)d_in[5];
    const float* W3      = (const float*)d_in[6];
    const float* b3      = (const float*)d_in[7];
    float* out = (float*)d_out;

    // Idempotent, host-side, not a stream op — safe under graph capture.
    cudaFuncSetAttribute(atomic_mlp_kernel,
                         cudaFuncAttributeMaxDynamicSharedMemorySize, SMEM_BYTES);

    dim3 grid(NROWS / TILE_N, NATOM);
    atomic_mlp_kernel<<<grid, NTHREADS, SMEM_BYTES>>>(
        desc, numbers, W1, b1, W2, b2, W3, b3, out);
}